// round 1
// baseline (speedup 1.0000x reference)
#include <cuda_runtime.h>
#include <math.h>

#define BB 16
#define LL1 512
#define LL2 512
#define EMB 300
#define AH 256
#define ATTD 250
#define HID 128
#define ATT_IN 812
#define RNN_IN 1280
#define GATES 512  // 4*HID

// ---------------- scratch (device globals; no allocation allowed) ----------------
__device__ float g_x1att[BB * LL1 * ATT_IN];   // 26.6 MB
__device__ float g_x2att[BB * LL2 * ATT_IN];   // 26.6 MB
__device__ float g_r1[BB * LL1 * 256];         // stride 256 (ATTD=250 padded)
__device__ float g_r2[BB * LL2 * 256];
__device__ float g_scores[BB * LL1 * LL2];     // 16.8 MB, reused per head
__device__ float g_x1cat[BB * LL1 * RNN_IN];   // 41.9 MB
__device__ float g_gin_f[LL1 * BB * GATES];    // [l][b][512]
__device__ float g_gin_b[LL1 * BB * GATES];

// ---------------- concat builders ----------------
__global__ void build_x1att(const float* __restrict__ w, const float* __restrict__ a0,
                            const float* __restrict__ a1) {
    int idx = blockIdx.x * blockDim.x + threadIdx.x;
    if (idx >= BB * LL1 * ATT_IN) return;
    int c = idx % ATT_IN;
    int r = idx / ATT_IN;
    float v;
    if (c < EMB) v = w[r * EMB + c];
    else if (c < EMB + AH) v = a0[r * AH + (c - EMB)];
    else v = a1[r * AH + (c - EMB - AH)];
    g_x1att[idx] = v;
}

__global__ void build_x2att(const float* __restrict__ w, const float* __restrict__ a0,
                            const float* __restrict__ a1) {
    int idx = blockIdx.x * blockDim.x + threadIdx.x;
    if (idx >= BB * LL2 * ATT_IN) return;
    int c = idx % ATT_IN;
    int r = idx / ATT_IN;
    float v;
    if (c < EMB) v = w[r * EMB + c];
    else if (c < EMB + AH) v = a0[r * AH + (c - EMB)];
    else v = a1[r * AH + (c - EMB - AH)];
    g_x2att[idx] = v;
}

__global__ void build_x1cat_head(const float* __restrict__ a0, const float* __restrict__ a1) {
    int idx = blockIdx.x * blockDim.x + threadIdx.x;
    if (idx >= BB * LL1 * 512) return;
    int c = idx % 512;
    int r = idx / 512;
    float v = (c < 256) ? a0[r * 256 + c] : a1[r * 256 + (c - 256)];
    g_x1cat[(long)r * RNN_IN + c] = v;
}

// ---------------- generic 64x64x16 tiled fp32 GEMM ----------------
// C[m,n] = sum_k A[m,k] * B'[k,n]   where B' = B^T if transB (B row-major NxK)
//                                   else B (row-major KxN)
// options: per-col bias, per-col vscale (applied after relu), relu,
//          permuted output row (b*512+l -> l*16+b) for LSTM gate layout,
//          batched via blockIdx.z with element strides.
__global__ void __launch_bounds__(256)
gemm64(const float* __restrict__ A, int lda, long sA,
       const float* __restrict__ Bm, int ldb, long sB, int transB,
       float* __restrict__ C, int ldc, long sC,
       int M, int N, int K,
       const float* __restrict__ bias, const float* __restrict__ vscale,
       int doRelu, int permuteOut) {
    __shared__ float As[16][64];
    __shared__ float Bs[16][64];

    int z = blockIdx.z;
    A += z * sA;
    Bm += z * sB;
    C += z * sC;

    int m0 = blockIdx.y * 64;
    int n0 = blockIdx.x * 64;
    int tid = threadIdx.x;
    int tx = tid & 15;   // n micro
    int ty = tid >> 4;   // m micro

    float acc[4][4];
#pragma unroll
    for (int i = 0; i < 4; i++)
#pragma unroll
        for (int j = 0; j < 4; j++) acc[i][j] = 0.f;

    for (int k0 = 0; k0 < K; k0 += 16) {
        // ---- load A tile (rows = M dim), coalesced-ish, guarded scalar ----
        {
            int row = tid >> 2;
            int kq = (tid & 3) * 4;
            int gm = m0 + row;
#pragma unroll
            for (int j = 0; j < 4; j++) {
                int gk = k0 + kq + j;
                As[kq + j][row] = (gm < M && gk < K) ? A[(long)gm * lda + gk] : 0.f;
            }
            if (transB) {
                int gn = n0 + row;
#pragma unroll
                for (int j = 0; j < 4; j++) {
                    int gk = k0 + kq + j;
                    Bs[kq + j][row] = (gn < N && gk < K) ? Bm[(long)gn * ldb + gk] : 0.f;
                }
            } else {
                int kk = tid >> 4;         // 0..15
                int nq = (tid & 15) * 4;   // 0..60
                int gk = k0 + kk;
#pragma unroll
                for (int j = 0; j < 4; j++) {
                    int gn = n0 + nq + j;
                    Bs[kk][nq + j] = (gk < K && gn < N) ? Bm[(long)gk * ldb + gn] : 0.f;
                }
            }
        }
        __syncthreads();

#pragma unroll
        for (int k = 0; k < 16; k++) {
            float4 a = *(const float4*)&As[k][ty * 4];
            float4 b = *(const float4*)&Bs[k][tx * 4];
            acc[0][0] += a.x * b.x; acc[0][1] += a.x * b.y; acc[0][2] += a.x * b.z; acc[0][3] += a.x * b.w;
            acc[1][0] += a.y * b.x; acc[1][1] += a.y * b.y; acc[1][2] += a.y * b.z; acc[1][3] += a.y * b.w;
            acc[2][0] += a.z * b.x; acc[2][1] += a.z * b.y; acc[2][2] += a.z * b.z; acc[2][3] += a.z * b.w;
            acc[3][0] += a.w * b.x; acc[3][1] += a.w * b.y; acc[3][2] += a.w * b.z; acc[3][3] += a.w * b.w;
        }
        __syncthreads();
    }

#pragma unroll
    for (int i = 0; i < 4; i++) {
        int row = m0 + ty * 4 + i;
        if (row >= M) continue;
        int orow = permuteOut ? ((row & 511) * 16 + (row >> 9)) : row;
#pragma unroll
        for (int j = 0; j < 4; j++) {
            int col = n0 + tx * 4 + j;
            if (col >= N) continue;
            float v = acc[i][j];
            if (bias) v += bias[col];
            if (doRelu) v = fmaxf(v, 0.f);
            if (vscale) v *= vscale[col];
            C[(long)orow * ldc + col] = v;
        }
    }
}

// ---------------- masked softmax over rows of g_scores ----------------
__global__ void softmax_rows(const unsigned char* __restrict__ mask) {
    int r = blockIdx.x;          // b*512 + l
    int b = r >> 9;
    float* row = g_scores + (long)r * LL2;
    __shared__ float red[256];
    int t = threadIdx.x;

    float v0 = row[t];
    float v1 = row[t + 256];
    if (mask[b * LL2 + t]) v0 = -3.402823466e38f;
    if (mask[b * LL2 + t + 256]) v1 = -3.402823466e38f;

    float mx = fmaxf(v0, v1);
    red[t] = mx;
    __syncthreads();
    for (int s = 128; s > 0; s >>= 1) {
        if (t < s) red[t] = fmaxf(red[t], red[t + s]);
        __syncthreads();
    }
    mx = red[0];
    __syncthreads();

    v0 = __expf(v0 - mx);
    v1 = __expf(v1 - mx);
    red[t] = v0 + v1;
    __syncthreads();
    for (int s = 128; s > 0; s >>= 1) {
        if (t < s) red[t] += red[t + s];
        __syncthreads();
    }
    float inv = 1.f / red[0];
    row[t] = v0 * inv;
    row[t + 256] = v1 * inv;
}

// ---------------- BiLSTM recurrence ----------------
// grid (16 batches, 2 dirs). 512 threads: thread j computes z[j] each step.
// Whh row j (128 floats): first 64 in registers, last 64 in shared (transposed,
// conflict-free). c state in registers of threads 0..127; h and z in shared.
__global__ void __launch_bounds__(512, 1)
lstm_kernel(const float* __restrict__ WhhF, const float* __restrict__ WhhB,
            float* __restrict__ out) {
    extern __shared__ float sm[];
    float* sWT = sm;               // [64][512]
    float* h_sh = sm + 64 * 512;   // [128]
    float* z_sh = h_sh + 128;      // [512]

    int b = blockIdx.x;
    int dir = blockIdx.y;
    const float* Whh = dir ? WhhB : WhhF;
    const float* gin = dir ? g_gin_b : g_gin_f;
    int j = threadIdx.x;

    float wreg[64];
#pragma unroll
    for (int k = 0; k < 64; k++) wreg[k] = Whh[j * HID + k];
    for (int k = 0; k < 64; k++) sWT[k * 512 + j] = Whh[j * HID + 64 + k];
    if (j < HID) h_sh[j] = 0.f;
    float c = 0.f;
    __syncthreads();

    for (int s = 0; s < LL1; s++) {
        int l = dir ? (LL1 - 1 - s) : s;
        float acc = gin[((long)l * BB + b) * GATES + j];
#pragma unroll
        for (int k = 0; k < 64; k += 4) {
            float4 hh = *(const float4*)&h_sh[k];
            acc += hh.x * wreg[k] + hh.y * wreg[k + 1] + hh.z * wreg[k + 2] + hh.w * wreg[k + 3];
        }
#pragma unroll
        for (int k = 0; k < 64; k += 4) {
            float4 hh = *(const float4*)&h_sh[64 + k];
            acc += hh.x * sWT[(k + 0) * 512 + j];
            acc += hh.y * sWT[(k + 1) * 512 + j];
            acc += hh.z * sWT[(k + 2) * 512 + j];
            acc += hh.w * sWT[(k + 3) * 512 + j];
        }
        z_sh[j] = acc;
        __syncthreads();
        if (j < HID) {
            float zi = z_sh[j], zf = z_sh[j + 128], zg = z_sh[j + 256], zo = z_sh[j + 384];
            float ii = 1.f / (1.f + __expf(-zi));
            float ff = 1.f / (1.f + __expf(-zf));
            float gg = tanhf(zg);
            float oo = 1.f / (1.f + __expf(-zo));
            c = ff * c + ii * gg;
            float h = oo * tanhf(c);
            h_sh[j] = h;
            out[((long)b * LL1 + l) * 256 + dir * HID + j] = h;
        }
        __syncthreads();
    }
}

// ---------------- launcher ----------------
extern "C" void kernel_launch(void* const* d_in, const int* in_sizes, int n_in,
                              void* d_out, int out_size) {
    const float* x1_word = (const float*)d_in[0];
    const float* x1_a0   = (const float*)d_in[1];
    const float* x1_a1   = (const float*)d_in[2];
    const float* x2_word = (const float*)d_in[3];
    const float* x2_a0   = (const float*)d_in[4];
    const float* x2_a1   = (const float*)d_in[5];
    const float* x2_a2   = (const float*)d_in[6];
    const unsigned char* x2_mask = (const unsigned char*)d_in[8];
    const float* W_attn  = (const float*)d_in[9];
    const float* v_attn  = (const float*)d_in[10];
    const float* Wih_f   = (const float*)d_in[11];
    const float* Whh_f   = (const float*)d_in[12];
    const float* b_f     = (const float*)d_in[13];
    const float* Wih_b   = (const float*)d_in[14];
    const float* Whh_b   = (const float*)d_in[15];
    const float* b_b     = (const float*)d_in[16];
    float* out = (float*)d_out;

    float *x1att, *x2att, *r1, *r2, *scores, *x1cat, *ginf, *ginb;
    cudaGetSymbolAddress((void**)&x1att, g_x1att);
    cudaGetSymbolAddress((void**)&x2att, g_x2att);
    cudaGetSymbolAddress((void**)&r1, g_r1);
    cudaGetSymbolAddress((void**)&r2, g_r2);
    cudaGetSymbolAddress((void**)&scores, g_scores);
    cudaGetSymbolAddress((void**)&x1cat, g_x1cat);
    cudaGetSymbolAddress((void**)&ginf, g_gin_f);
    cudaGetSymbolAddress((void**)&ginb, g_gin_b);

    // concat inputs
    {
        int n1 = BB * LL1 * ATT_IN;
        build_x1att<<<(n1 + 255) / 256, 256>>>(x1_word, x1_a0, x1_a1);
        int n2 = BB * LL2 * ATT_IN;
        build_x2att<<<(n2 + 255) / 256, 256>>>(x2_word, x2_a0, x2_a1);
        int n3 = BB * LL1 * 512;
        build_x1cat_head<<<(n3 + 255) / 256, 256>>>(x1_a0, x1_a1);
    }

    const float* x2_list[3] = {x2_a0, x2_a1, x2_a2};
    for (int i = 0; i < 3; i++) {
        const float* Wi = W_attn + (long)i * ATTD * ATT_IN;
        const float* vi = v_attn + i * ATTD;

        // r1 = relu(x1att @ Wi^T)         [8192 x 250], stride 256
        gemm64<<<dim3(4, 128, 1), 256>>>(x1att, ATT_IN, 0, Wi, ATT_IN, 0, 1,
                                         r1, 256, 0, BB * LL1, ATTD, ATT_IN,
                                         nullptr, nullptr, 1, 0);
        // r2 = relu(x2att @ Wi^T) * v     [8192 x 250]
        gemm64<<<dim3(4, 128, 1), 256>>>(x2att, ATT_IN, 0, Wi, ATT_IN, 0, 1,
                                         r2, 256, 0, BB * LL2, ATTD, ATT_IN,
                                         nullptr, vi, 1, 0);
        // scores[b] = r1[b] @ r2[b]^T     batched 16 x [512 x 512], K=250
        gemm64<<<dim3(8, 8, 16), 256>>>(r1, 256, (long)512 * 256,
                                        r2, 256, (long)512 * 256, 1,
                                        scores, 512, (long)512 * 512,
                                        LL1, LL2, ATTD, nullptr, nullptr, 0, 0);
        // softmax (with x2 mask)
        softmax_rows<<<BB * LL1, 256>>>(x2_mask);
        // piece_i[b] = alpha[b] @ x2_list[i][b]   -> x1cat cols [512+256i, +256)
        gemm64<<<dim3(4, 8, 16), 256>>>(scores, 512, (long)512 * 512,
                                        x2_list[i], 256, (long)512 * 256, 0,
                                        x1cat + 512 + 256 * i, RNN_IN, (long)512 * RNN_IN,
                                        LL1, AH, LL2, nullptr, nullptr, 0, 0);
    }

    // g_in = x1cat @ Wih^T + b, stored as [l][b][512]
    gemm64<<<dim3(8, 128, 1), 256>>>(x1cat, RNN_IN, 0, Wih_f, RNN_IN, 0, 1,
                                     ginf, GATES, 0, BB * LL1, GATES, RNN_IN,
                                     b_f, nullptr, 0, 1);
    gemm64<<<dim3(8, 128, 1), 256>>>(x1cat, RNN_IN, 0, Wih_b, RNN_IN, 0, 1,
                                     ginb, GATES, 0, BB * LL1, GATES, RNN_IN,
                                     b_b, nullptr, 0, 1);

    // BiLSTM
    size_t smem = (size_t)(64 * 512 + 128 + 512) * sizeof(float);
    cudaFuncSetAttribute(lstm_kernel, cudaFuncAttributeMaxDynamicSharedMemorySize, (int)smem);
    lstm_kernel<<<dim3(16, 2), 512, smem>>>(Whh_f, Whh_b, out);
}

// round 2
// speedup vs baseline: 1.2624x; 1.2624x over previous
#include <cuda_runtime.h>
#include <math.h>

#define BB 16
#define LL1 512
#define LL2 512
#define EMB 300
#define AH 256
#define ATTD 250
#define HID 128
#define ATT_IN 812
#define RNN_IN 1280
#define GATES 512  // 4*HID

// ---------------- scratch (device globals; no allocation allowed) ----------------
__device__ float g_x1att[BB * LL1 * ATT_IN];
__device__ float g_x2att[BB * LL2 * ATT_IN];
__device__ float g_r1[BB * LL1 * 256];         // ATTD=250 padded to 256
__device__ float g_r2[BB * LL2 * 256];
__device__ float g_scores[BB * LL1 * LL2];
__device__ float g_x1cat[BB * LL1 * RNN_IN];
__device__ float g_gin_f[LL1 * BB * GATES];    // [l][b][512]
__device__ float g_gin_b[LL1 * BB * GATES];

// ---------------- concat builders ----------------
__global__ void build_x1att(const float* __restrict__ w, const float* __restrict__ a0,
                            const float* __restrict__ a1) {
    int idx = blockIdx.x * blockDim.x + threadIdx.x;
    if (idx >= BB * LL1 * ATT_IN) return;
    int c = idx % ATT_IN;
    int r = idx / ATT_IN;
    float v;
    if (c < EMB) v = w[r * EMB + c];
    else if (c < EMB + AH) v = a0[r * AH + (c - EMB)];
    else v = a1[r * AH + (c - EMB - AH)];
    g_x1att[idx] = v;
}

__global__ void build_x2att(const float* __restrict__ w, const float* __restrict__ a0,
                            const float* __restrict__ a1) {
    int idx = blockIdx.x * blockDim.x + threadIdx.x;
    if (idx >= BB * LL2 * ATT_IN) return;
    int c = idx % ATT_IN;
    int r = idx / ATT_IN;
    float v;
    if (c < EMB) v = w[r * EMB + c];
    else if (c < EMB + AH) v = a0[r * AH + (c - EMB)];
    else v = a1[r * AH + (c - EMB - AH)];
    g_x2att[idx] = v;
}

__global__ void build_x1cat_head(const float* __restrict__ a0, const float* __restrict__ a1) {
    int idx = blockIdx.x * blockDim.x + threadIdx.x;
    if (idx >= BB * LL1 * 512) return;
    int c = idx % 512;
    int r = idx / 512;
    float v = (c < 256) ? a0[r * 256 + c] : a1[r * 256 + (c - 256)];
    g_x1cat[(long)r * RNN_IN + c] = v;
}

// ---------------- 128x128x16 tiled fp32 GEMM, 8x8 microtile ----------------
// C[m,n] = sum_k A[m,k] * B'[k,n]; B' = B^T if transB (B row-major NxK) else B (KxN).
// Requirements exploited: M is a multiple of 128; N multiple of 128 when !transB;
// all ld* divisible by 4 (float4-aligned rows).
__global__ void __launch_bounds__(256, 2)
gemm128(const float* __restrict__ A, int lda, long sA,
        const float* __restrict__ Bm, int ldb, long sB, int transB,
        float* __restrict__ C, int ldc, long sC,
        int M, int N, int K,
        const float* __restrict__ bias, const float* __restrict__ vscale,
        int doRelu, int permuteOut) {
    __shared__ float As[16][128];
    __shared__ float Bs[16][128];

    int z = blockIdx.z;
    A += z * sA;
    Bm += z * sB;
    C += z * sC;

    int m0 = blockIdx.y * 128;
    int n0 = blockIdx.x * 128;
    int tid = threadIdx.x;
    int tx = tid & 15;   // n micro (8 cols)
    int ty = tid >> 4;   // m micro (8 rows)

    float acc[8][8];
#pragma unroll
    for (int i = 0; i < 8; i++)
#pragma unroll
        for (int j = 0; j < 8; j++) acc[i][j] = 0.f;

    // loader indices
    int lm = tid >> 1;          // 0..127 (row within tile for A / transB-B)
    int lk = (tid & 1) * 8;     // 0 or 8
    int bk = tid >> 4;          // 0..15 (k for non-trans B)
    int bn = (tid & 15) * 8;    // 0..120

    for (int k0 = 0; k0 < K; k0 += 16) {
        int ktail = K - k0;

        // ---- A tile: As[k][m] ----
        {
            const float* ap = A + (long)(m0 + lm) * lda + k0 + lk;
            if (ktail >= 16) {
                float4 v0 = *(const float4*)ap;
                float4 v1 = *(const float4*)(ap + 4);
                As[lk + 0][lm] = v0.x; As[lk + 1][lm] = v0.y;
                As[lk + 2][lm] = v0.z; As[lk + 3][lm] = v0.w;
                As[lk + 4][lm] = v1.x; As[lk + 5][lm] = v1.y;
                As[lk + 6][lm] = v1.z; As[lk + 7][lm] = v1.w;
            } else {
#pragma unroll
                for (int j = 0; j < 8; j++)
                    As[lk + j][lm] = (lk + j < ktail) ? ap[j] : 0.f;
            }
        }

        // ---- B tile: Bs[k][n] ----
        if (transB) {
            int gn = n0 + lm;
            const float* bp = Bm + (long)gn * ldb + k0 + lk;
            bool nok = gn < N;
            if (nok && ktail >= 16) {
                float4 v0 = *(const float4*)bp;
                float4 v1 = *(const float4*)(bp + 4);
                Bs[lk + 0][lm] = v0.x; Bs[lk + 1][lm] = v0.y;
                Bs[lk + 2][lm] = v0.z; Bs[lk + 3][lm] = v0.w;
                Bs[lk + 4][lm] = v1.x; Bs[lk + 5][lm] = v1.y;
                Bs[lk + 6][lm] = v1.z; Bs[lk + 7][lm] = v1.w;
            } else {
#pragma unroll
                for (int j = 0; j < 8; j++)
                    Bs[lk + j][lm] = (nok && lk + j < ktail) ? bp[j] : 0.f;
            }
        } else {
            const float* bp = Bm + (long)(k0 + bk) * ldb + n0 + bn;
            if (bk < ktail) {
                float4 v0 = *(const float4*)bp;
                float4 v1 = *(const float4*)(bp + 4);
                Bs[bk][bn + 0] = v0.x; Bs[bk][bn + 1] = v0.y;
                Bs[bk][bn + 2] = v0.z; Bs[bk][bn + 3] = v0.w;
                Bs[bk][bn + 4] = v1.x; Bs[bk][bn + 5] = v1.y;
                Bs[bk][bn + 6] = v1.z; Bs[bk][bn + 7] = v1.w;
            } else {
#pragma unroll
                for (int j = 0; j < 8; j++) Bs[bk][bn + j] = 0.f;
            }
        }
        __syncthreads();

#pragma unroll
        for (int k = 0; k < 16; k++) {
            float ar[8], br[8];
            *(float4*)&ar[0] = *(const float4*)&As[k][ty * 8];
            *(float4*)&ar[4] = *(const float4*)&As[k][ty * 8 + 4];
            *(float4*)&br[0] = *(const float4*)&Bs[k][tx * 8];
            *(float4*)&br[4] = *(const float4*)&Bs[k][tx * 8 + 4];
#pragma unroll
            for (int i = 0; i < 8; i++)
#pragma unroll
                for (int j = 0; j < 8; j++)
                    acc[i][j] += ar[i] * br[j];
        }
        __syncthreads();
    }

#pragma unroll
    for (int i = 0; i < 8; i++) {
        int row = m0 + ty * 8 + i;   // M is a multiple of 128 -> always valid
        int orow = permuteOut ? ((row & 511) * 16 + (row >> 9)) : row;
        float* cp = C + (long)orow * ldc;
#pragma unroll
        for (int j = 0; j < 8; j++) {
            int col = n0 + tx * 8 + j;
            if (col >= N) continue;
            float v = acc[i][j];
            if (bias) v += bias[col];
            if (doRelu) v = fmaxf(v, 0.f);
            if (vscale) v *= vscale[col];
            cp[col] = v;
        }
    }
}

// ---------------- masked softmax over rows of g_scores ----------------
__global__ void softmax_rows(const unsigned char* __restrict__ mask) {
    int r = blockIdx.x;          // b*512 + l
    int b = r >> 9;
    float* row = g_scores + (long)r * LL2;
    __shared__ float red[256];
    int t = threadIdx.x;

    float v0 = row[t];
    float v1 = row[t + 256];
    if (mask[b * LL2 + t]) v0 = -3.402823466e38f;
    if (mask[b * LL2 + t + 256]) v1 = -3.402823466e38f;

    float mx = fmaxf(v0, v1);
    red[t] = mx;
    __syncthreads();
    for (int s = 128; s > 0; s >>= 1) {
        if (t < s) red[t] = fmaxf(red[t], red[t + s]);
        __syncthreads();
    }
    mx = red[0];
    __syncthreads();

    v0 = __expf(v0 - mx);
    v1 = __expf(v1 - mx);
    red[t] = v0 + v1;
    __syncthreads();
    for (int s = 128; s > 0; s >>= 1) {
        if (t < s) red[t] += red[t + s];
        __syncthreads();
    }
    float inv = 1.f / red[0];
    row[t] = v0 * inv;
    row[t + 256] = v1 * inv;
}

// ---------------- BiLSTM recurrence ----------------
// grid (16 batches, 2 dirs), 512 threads; thread j computes z[j] per step.
// Whh row j: k 0..63 in registers; k 64..127 in shared as float4 tiles
// sW4[k4][j] (conflict-free LDS.128). gin for next step prefetched via LDG.
__global__ void __launch_bounds__(512, 1)
lstm_kernel(const float* __restrict__ WhhF, const float* __restrict__ WhhB,
            float* __restrict__ out) {
    extern __shared__ float sm[];
    float4* sW4 = (float4*)sm;              // [16][512] float4 = 128KB
    float* h_sh = sm + 16 * 512 * 4;        // [128]
    float* z_sh = h_sh + 128;               // [512]

    int b = blockIdx.x;
    int dir = blockIdx.y;
    const float* Whh = dir ? WhhB : WhhF;
    const float* gin = dir ? g_gin_b : g_gin_f;
    int j = threadIdx.x;

    float wreg[64];
#pragma unroll
    for (int k = 0; k < 64; k++) wreg[k] = Whh[j * HID + k];
#pragma unroll
    for (int k4 = 0; k4 < 16; k4++) {
        float4 w;
        w.x = Whh[j * HID + 64 + k4 * 4 + 0];
        w.y = Whh[j * HID + 64 + k4 * 4 + 1];
        w.z = Whh[j * HID + 64 + k4 * 4 + 2];
        w.w = Whh[j * HID + 64 + k4 * 4 + 3];
        sW4[k4 * 512 + j] = w;
    }
    if (j < HID) h_sh[j] = 0.f;
    float c = 0.f;
    __syncthreads();

    int l0 = dir ? (LL1 - 1) : 0;
    float gcur = gin[((long)l0 * BB + b) * GATES + j];

    for (int s = 0; s < LL1; s++) {
        int l = dir ? (LL1 - 1 - s) : s;
        // prefetch next step's input gate
        float gnext = 0.f;
        if (s + 1 < LL1) {
            int ln = dir ? (LL1 - 2 - s) : (s + 1);
            gnext = gin[((long)ln * BB + b) * GATES + j];
        }

        float acc = gcur;
#pragma unroll
        for (int k = 0; k < 64; k += 4) {
            float4 hh = *(const float4*)&h_sh[k];
            acc += hh.x * wreg[k] + hh.y * wreg[k + 1] + hh.z * wreg[k + 2] + hh.w * wreg[k + 3];
        }
#pragma unroll
        for (int k4 = 0; k4 < 16; k4++) {
            float4 hh = *(const float4*)&h_sh[64 + k4 * 4];
            float4 w = sW4[k4 * 512 + j];
            acc += hh.x * w.x + hh.y * w.y + hh.z * w.z + hh.w * w.w;
        }
        z_sh[j] = acc;
        __syncthreads();
        if (j < HID) {
            float zi = z_sh[j], zf = z_sh[j + 128], zg = z_sh[j + 256], zo = z_sh[j + 384];
            float ii = 1.f / (1.f + __expf(-zi));
            float ff = 1.f / (1.f + __expf(-zf));
            float gg = tanhf(zg);
            float oo = 1.f / (1.f + __expf(-zo));
            c = ff * c + ii * gg;
            float h = oo * tanhf(c);
            h_sh[j] = h;
            out[((long)b * LL1 + l) * 256 + dir * HID + j] = h;
        }
        gcur = gnext;
        __syncthreads();
    }
}

// ---------------- launcher ----------------
extern "C" void kernel_launch(void* const* d_in, const int* in_sizes, int n_in,
                              void* d_out, int out_size) {
    const float* x1_word = (const float*)d_in[0];
    const float* x1_a0   = (const float*)d_in[1];
    const float* x1_a1   = (const float*)d_in[2];
    const float* x2_word = (const float*)d_in[3];
    const float* x2_a0   = (const float*)d_in[4];
    const float* x2_a1   = (const float*)d_in[5];
    const float* x2_a2   = (const float*)d_in[6];
    const unsigned char* x2_mask = (const unsigned char*)d_in[8];
    const float* W_attn  = (const float*)d_in[9];
    const float* v_attn  = (const float*)d_in[10];
    const float* Wih_f   = (const float*)d_in[11];
    const float* Whh_f   = (const float*)d_in[12];
    const float* b_f     = (const float*)d_in[13];
    const float* Wih_b   = (const float*)d_in[14];
    const float* Whh_b   = (const float*)d_in[15];
    const float* b_b     = (const float*)d_in[16];
    float* out = (float*)d_out;

    float *x1att, *x2att, *r1, *r2, *scores, *x1cat, *ginf, *ginb;
    cudaGetSymbolAddress((void**)&x1att, g_x1att);
    cudaGetSymbolAddress((void**)&x2att, g_x2att);
    cudaGetSymbolAddress((void**)&r1, g_r1);
    cudaGetSymbolAddress((void**)&r2, g_r2);
    cudaGetSymbolAddress((void**)&scores, g_scores);
    cudaGetSymbolAddress((void**)&x1cat, g_x1cat);
    cudaGetSymbolAddress((void**)&ginf, g_gin_f);
    cudaGetSymbolAddress((void**)&ginb, g_gin_b);

    // concat inputs
    {
        int n1 = BB * LL1 * ATT_IN;
        build_x1att<<<(n1 + 255) / 256, 256>>>(x1_word, x1_a0, x1_a1);
        int n2 = BB * LL2 * ATT_IN;
        build_x2att<<<(n2 + 255) / 256, 256>>>(x2_word, x2_a0, x2_a1);
        int n3 = BB * LL1 * 512;
        build_x1cat_head<<<(n3 + 255) / 256, 256>>>(x1_a0, x1_a1);
    }

    const float* x2_list[3] = {x2_a0, x2_a1, x2_a2};
    for (int i = 0; i < 3; i++) {
        const float* Wi = W_attn + (long)i * ATTD * ATT_IN;
        const float* vi = v_attn + i * ATTD;

        // r1 = relu(x1att @ Wi^T)         [8192 x 250], stride 256
        gemm128<<<dim3(2, 64, 1), 256>>>(x1att, ATT_IN, 0, Wi, ATT_IN, 0, 1,
                                         r1, 256, 0, BB * LL1, ATTD, ATT_IN,
                                         nullptr, nullptr, 1, 0);
        // r2 = relu(x2att @ Wi^T) * v
        gemm128<<<dim3(2, 64, 1), 256>>>(x2att, ATT_IN, 0, Wi, ATT_IN, 0, 1,
                                         r2, 256, 0, BB * LL2, ATTD, ATT_IN,
                                         nullptr, vi, 1, 0);
        // scores[b] = r1[b] @ r2[b]^T     batched 16 x [512 x 512], K=250
        gemm128<<<dim3(4, 4, 16), 256>>>(r1, 256, (long)512 * 256,
                                         r2, 256, (long)512 * 256, 1,
                                         scores, 512, (long)512 * 512,
                                         LL1, LL2, ATTD, nullptr, nullptr, 0, 0);
        // softmax (with x2 mask)
        softmax_rows<<<BB * LL1, 256>>>(x2_mask);
        // piece_i[b] = alpha[b] @ x2_list[i][b] -> x1cat cols [512+256i, +256)
        gemm128<<<dim3(2, 4, 16), 256>>>(scores, 512, (long)512 * 512,
                                         x2_list[i], 256, (long)512 * 256, 0,
                                         x1cat + 512 + 256 * i, RNN_IN, (long)512 * RNN_IN,
                                         LL1, AH, LL2, nullptr, nullptr, 0, 0);
    }

    // g_in = x1cat @ Wih^T + b, stored as [l][b][512]
    gemm128<<<dim3(4, 64, 1), 256>>>(x1cat, RNN_IN, 0, Wih_f, RNN_IN, 0, 1,
                                     ginf, GATES, 0, BB * LL1, GATES, RNN_IN,
                                     b_f, nullptr, 0, 1);
    gemm128<<<dim3(4, 64, 1), 256>>>(x1cat, RNN_IN, 0, Wih_b, RNN_IN, 0, 1,
                                     ginb, GATES, 0, BB * LL1, GATES, RNN_IN,
                                     b_b, nullptr, 0, 1);

    // BiLSTM
    size_t smem = (size_t)(16 * 512 * 4 + 128 + 512) * sizeof(float);
    cudaFuncSetAttribute(lstm_kernel, cudaFuncAttributeMaxDynamicSharedMemorySize, (int)smem);
    lstm_kernel<<<dim3(16, 2), 512, smem>>>(Whh_f, Whh_b, out);
}

// round 4
// speedup vs baseline: 1.4002x; 1.1091x over previous
#include <cuda_runtime.h>
#include <math.h>
#include <stdint.h>

#define BB 16
#define LL1 512
#define LL2 512
#define EMB 300
#define AH 256
#define ATTD 250
#define HID 128
#define ATT_IN 812
#define RNN_IN 1280
#define GATES 512  // 4*HID

// ---------------- scratch (device globals; no allocation allowed) ----------------
__device__ float g_x1att[BB * LL1 * ATT_IN];
__device__ float g_x2att[BB * LL2 * ATT_IN];
__device__ float g_r1[BB * LL1 * 256];         // ATTD=250 padded to 256
__device__ float g_r2[BB * LL2 * 256];
__device__ float g_scores[BB * LL1 * LL2];
__device__ float g_x1cat[BB * LL1 * RNN_IN];
__device__ float g_gin_f[LL1 * BB * GATES];    // [l][b][512]
__device__ float g_gin_b[LL1 * BB * GATES];

// ---------------- concat builders ----------------
__global__ void build_x1att(const float* __restrict__ w, const float* __restrict__ a0,
                            const float* __restrict__ a1) {
    int idx = blockIdx.x * blockDim.x + threadIdx.x;
    if (idx >= BB * LL1 * ATT_IN) return;
    int c = idx % ATT_IN;
    int r = idx / ATT_IN;
    float v;
    if (c < EMB) v = w[r * EMB + c];
    else if (c < EMB + AH) v = a0[r * AH + (c - EMB)];
    else v = a1[r * AH + (c - EMB - AH)];
    g_x1att[idx] = v;
}

__global__ void build_x2att(const float* __restrict__ w, const float* __restrict__ a0,
                            const float* __restrict__ a1) {
    int idx = blockIdx.x * blockDim.x + threadIdx.x;
    if (idx >= BB * LL2 * ATT_IN) return;
    int c = idx % ATT_IN;
    int r = idx / ATT_IN;
    float v;
    if (c < EMB) v = w[r * EMB + c];
    else if (c < EMB + AH) v = a0[r * AH + (c - EMB)];
    else v = a1[r * AH + (c - EMB - AH)];
    g_x2att[idx] = v;
}

__global__ void build_x1cat_head(const float* __restrict__ a0, const float* __restrict__ a1) {
    int idx = blockIdx.x * blockDim.x + threadIdx.x;
    if (idx >= BB * LL1 * 512) return;
    int c = idx % 512;
    int r = idx / 512;
    float v = (c < 256) ? a0[r * 256 + c] : a1[r * 256 + (c - 256)];
    g_x1cat[(long)r * RNN_IN + c] = v;
}

// ---------------- tf32 helpers ----------------
__device__ __forceinline__ float cvt_tf32(float x) {
    uint32_t u;
    asm("cvt.rna.tf32.f32 %0, %1;" : "=r"(u) : "f"(x));
    return __uint_as_float(u);
}

__device__ __forceinline__ void mma_tf32(float* d, const uint32_t* a, const uint32_t* b) {
    asm volatile(
        "mma.sync.aligned.m16n8k8.row.col.f32.tf32.tf32.f32 "
        "{%0,%1,%2,%3}, {%4,%5,%6,%7}, {%8,%9}, {%0,%1,%2,%3};"
        : "+f"(d[0]), "+f"(d[1]), "+f"(d[2]), "+f"(d[3])
        : "r"(a[0]), "r"(a[1]), "r"(a[2]), "r"(a[3]), "r"(b[0]), "r"(b[1]));
}

// ---------- 3xTF32 tensor-core GEMM: 128x128 block, 8 warps (2m x 4n) ----------
// C[m,n] = sum_k A[m,k]*B'[k,n]; B' = B^T if transB (B row-major NxK) else B (KxN).
// M must be a multiple of 128. K-step 16. Each operand split big+small (tf32);
// acc += Ab*Bb + Ab*Bs + As*Bb.
#define LDS_PAD 20

__global__ void __launch_bounds__(256)
gemm_tc(const float* __restrict__ A, int lda, long sA,
        const float* __restrict__ Bm, int ldb, long sB, int transB,
        float* __restrict__ C, int ldc, long sC,
        int M, int N, int K,
        const float* __restrict__ bias, const float* __restrict__ vscale,
        int doRelu, int permuteOut) {
    __shared__ float AsB[128 * LDS_PAD];
    __shared__ float AsS[128 * LDS_PAD];
    __shared__ float BsB[128 * LDS_PAD];
    __shared__ float BsS[128 * LDS_PAD];

    int z = blockIdx.z;
    A += z * sA;
    Bm += z * sB;
    C += z * sC;

    int m0 = blockIdx.y * 128;
    int n0 = blockIdx.x * 128;
    int tid = threadIdx.x;
    int wid = tid >> 5;
    int lane = tid & 31;
    int g = lane >> 2;     // 0..7
    int tg = lane & 3;     // 0..3
    int warp_m = wid & 1;  // 64 rows each
    int warp_n = wid >> 1; // 32 cols each

    float acc[4][4][4];
#pragma unroll
    for (int i = 0; i < 4; i++)
#pragma unroll
        for (int j = 0; j < 4; j++)
#pragma unroll
            for (int q = 0; q < 4; q++) acc[i][j][q] = 0.f;

    // staging indices
    int arow = tid >> 1;           // 0..127
    int akh = (tid & 1) * 8;       // 0 or 8
    int bk = tid >> 4;             // non-trans: k 0..15
    int bn4 = (tid & 15) * 8;      // non-trans: n 0..120

    float ar[8], br[8];

    // ---- prologue load (k0 = 0) ----
    {
        const float* ap = A + (long)(m0 + arow) * lda + akh;
        if (16 <= K) {
            float4 v0 = *(const float4*)ap;
            float4 v1 = *(const float4*)(ap + 4);
            ar[0] = v0.x; ar[1] = v0.y; ar[2] = v0.z; ar[3] = v0.w;
            ar[4] = v1.x; ar[5] = v1.y; ar[6] = v1.z; ar[7] = v1.w;
        } else {
#pragma unroll
            for (int j = 0; j < 8; j++) ar[j] = (akh + j < K) ? ap[j] : 0.f;
        }
        if (transB) {
            bool nok = (n0 + arow) < N;
            const float* bp = Bm + (long)(n0 + arow) * ldb + akh;
            if (nok && 16 <= K) {
                float4 v0 = *(const float4*)bp;
                float4 v1 = *(const float4*)(bp + 4);
                br[0] = v0.x; br[1] = v0.y; br[2] = v0.z; br[3] = v0.w;
                br[4] = v1.x; br[5] = v1.y; br[6] = v1.z; br[7] = v1.w;
            } else {
#pragma unroll
                for (int j = 0; j < 8; j++) br[j] = (nok && akh + j < K) ? bp[j] : 0.f;
            }
        } else {
            bool kok = bk < K;
            const float* bp = Bm + (long)bk * ldb + n0 + bn4;
            if (kok && n0 + bn4 + 8 <= N) {
                float4 v0 = *(const float4*)bp;
                float4 v1 = *(const float4*)(bp + 4);
                br[0] = v0.x; br[1] = v0.y; br[2] = v0.z; br[3] = v0.w;
                br[4] = v1.x; br[5] = v1.y; br[6] = v1.z; br[7] = v1.w;
            } else {
#pragma unroll
                for (int j = 0; j < 8; j++) br[j] = (kok && n0 + bn4 + j < N) ? bp[j] : 0.f;
            }
        }
    }

    for (int k0 = 0; k0 < K; k0 += 16) {
        // ---- split + store staged regs to smem ----
#pragma unroll
        for (int j = 0; j < 8; j++) {
            float big = cvt_tf32(ar[j]);
            AsB[arow * LDS_PAD + akh + j] = big;
            AsS[arow * LDS_PAD + akh + j] = cvt_tf32(ar[j] - big);
        }
        if (transB) {
#pragma unroll
            for (int j = 0; j < 8; j++) {
                float big = cvt_tf32(br[j]);
                BsB[arow * LDS_PAD + akh + j] = big;
                BsS[arow * LDS_PAD + akh + j] = cvt_tf32(br[j] - big);
            }
        } else {
#pragma unroll
            for (int j = 0; j < 8; j++) {
                float big = cvt_tf32(br[j]);
                BsB[(bn4 + j) * LDS_PAD + bk] = big;
                BsS[(bn4 + j) * LDS_PAD + bk] = cvt_tf32(br[j] - big);
            }
        }
        __syncthreads();

        // ---- prefetch next tile into regs ----
        int kn = k0 + 16;
        if (kn < K) {
            const float* ap = A + (long)(m0 + arow) * lda + kn + akh;
            if (kn + 16 <= K) {
                float4 v0 = *(const float4*)ap;
                float4 v1 = *(const float4*)(ap + 4);
                ar[0] = v0.x; ar[1] = v0.y; ar[2] = v0.z; ar[3] = v0.w;
                ar[4] = v1.x; ar[5] = v1.y; ar[6] = v1.z; ar[7] = v1.w;
            } else {
#pragma unroll
                for (int j = 0; j < 8; j++) ar[j] = (kn + akh + j < K) ? ap[j] : 0.f;
            }
            if (transB) {
                bool nok = (n0 + arow) < N;
                const float* bp = Bm + (long)(n0 + arow) * ldb + kn + akh;
                if (nok && kn + 16 <= K) {
                    float4 v0 = *(const float4*)bp;
                    float4 v1 = *(const float4*)(bp + 4);
                    br[0] = v0.x; br[1] = v0.y; br[2] = v0.z; br[3] = v0.w;
                    br[4] = v1.x; br[5] = v1.y; br[6] = v1.z; br[7] = v1.w;
                } else {
#pragma unroll
                    for (int j = 0; j < 8; j++) br[j] = (nok && kn + akh + j < K) ? bp[j] : 0.f;
                }
            } else {
                bool kok = kn + bk < K;
                const float* bp = Bm + (long)(kn + bk) * ldb + n0 + bn4;
                if (kok && n0 + bn4 + 8 <= N) {
                    float4 v0 = *(const float4*)bp;
                    float4 v1 = *(const float4*)(bp + 4);
                    br[0] = v0.x; br[1] = v0.y; br[2] = v0.z; br[3] = v0.w;
                    br[4] = v1.x; br[5] = v1.y; br[6] = v1.z; br[7] = v1.w;
                } else {
#pragma unroll
                    for (int j = 0; j < 8; j++) br[j] = (kok && n0 + bn4 + j < N) ? bp[j] : 0.f;
                }
            }
        }

        // ---- MMA over two k8 slices, 3xTF32 ----
#pragma unroll
        for (int k8 = 0; k8 < 2; k8++) {
            int kb = k8 * 8;
            uint32_t afB[4][4], afS[4][4];
#pragma unroll
            for (int mi = 0; mi < 4; mi++) {
                int r = warp_m * 64 + mi * 16;
                int i0 = (r + g) * LDS_PAD + kb + tg;
                int i1 = (r + g + 8) * LDS_PAD + kb + tg;
                afB[mi][0] = __float_as_uint(AsB[i0]);
                afB[mi][1] = __float_as_uint(AsB[i1]);
                afB[mi][2] = __float_as_uint(AsB[i0 + 4]);
                afB[mi][3] = __float_as_uint(AsB[i1 + 4]);
                afS[mi][0] = __float_as_uint(AsS[i0]);
                afS[mi][1] = __float_as_uint(AsS[i1]);
                afS[mi][2] = __float_as_uint(AsS[i0 + 4]);
                afS[mi][3] = __float_as_uint(AsS[i1 + 4]);
            }
            uint32_t bfB[4][2], bfS[4][2];
#pragma unroll
            for (int nj = 0; nj < 4; nj++) {
                int c = (warp_n * 32 + nj * 8 + g) * LDS_PAD + kb + tg;
                bfB[nj][0] = __float_as_uint(BsB[c]);
                bfB[nj][1] = __float_as_uint(BsB[c + 4]);
                bfS[nj][0] = __float_as_uint(BsS[c]);
                bfS[nj][1] = __float_as_uint(BsS[c + 4]);
            }
#pragma unroll
            for (int mi = 0; mi < 4; mi++)
#pragma unroll
                for (int nj = 0; nj < 4; nj++) {
                    mma_tf32(acc[mi][nj], afS[mi], bfB[nj]);
                    mma_tf32(acc[mi][nj], afB[mi], bfS[nj]);
                    mma_tf32(acc[mi][nj], afB[mi], bfB[nj]);
                }
        }
        __syncthreads();
    }

    // ---- epilogue ----
#pragma unroll
    for (int mi = 0; mi < 4; mi++) {
        int r0 = m0 + warp_m * 64 + mi * 16 + g;
        int r1 = r0 + 8;
        int o0 = permuteOut ? ((r0 & 511) * 16 + (r0 >> 9)) : r0;
        int o1 = permuteOut ? ((r1 & 511) * 16 + (r1 >> 9)) : r1;
        float* c0p = C + (long)o0 * ldc;
        float* c1p = C + (long)o1 * ldc;
#pragma unroll
        for (int nj = 0; nj < 4; nj++) {
            int col = n0 + warp_n * 32 + nj * 8 + 2 * tg;
            if (col >= N) continue;   // N even -> pair-guard safe
            float v0 = acc[mi][nj][0], v1 = acc[mi][nj][1];
            float v2 = acc[mi][nj][2], v3 = acc[mi][nj][3];
            if (bias) {
                float b0 = bias[col], b1 = bias[col + 1];
                v0 += b0; v1 += b1; v2 += b0; v3 += b1;
            }
            if (doRelu) {
                v0 = fmaxf(v0, 0.f); v1 = fmaxf(v1, 0.f);
                v2 = fmaxf(v2, 0.f); v3 = fmaxf(v3, 0.f);
            }
            if (vscale) {
                float s0 = vscale[col], s1 = vscale[col + 1];
                v0 *= s0; v1 *= s1; v2 *= s0; v3 *= s1;
            }
            *(float2*)(c0p + col) = make_float2(v0, v1);
            *(float2*)(c1p + col) = make_float2(v2, v3);
        }
    }
}

// ---------------- masked softmax over rows of g_scores ----------------
__global__ void softmax_rows(const unsigned char* __restrict__ mask) {
    int r = blockIdx.x;          // b*512 + l
    int b = r >> 9;
    float* row = g_scores + (long)r * LL2;
    __shared__ float red[256];
    int t = threadIdx.x;

    float v0 = row[t];
    float v1 = row[t + 256];
    if (mask[b * LL2 + t]) v0 = -3.402823466e38f;
    if (mask[b * LL2 + t + 256]) v1 = -3.402823466e38f;

    float mx = fmaxf(v0, v1);
    red[t] = mx;
    __syncthreads();
    for (int s = 128; s > 0; s >>= 1) {
        if (t < s) red[t] = fmaxf(red[t], red[t + s]);
        __syncthreads();
    }
    mx = red[0];
    __syncthreads();

    v0 = __expf(v0 - mx);
    v1 = __expf(v1 - mx);
    red[t] = v0 + v1;
    __syncthreads();
    for (int s = 128; s > 0; s >>= 1) {
        if (t < s) red[t] += red[t + s];
        __syncthreads();
    }
    float inv = 1.f / red[0];
    row[t] = v0 * inv;
    row[t + 256] = v1 * inv;
}

// ---------------- BiLSTM recurrence ----------------
__global__ void __launch_bounds__(512, 1)
lstm_kernel(const float* __restrict__ WhhF, const float* __restrict__ WhhB,
            float* __restrict__ out) {
    extern __shared__ float sm[];
    float4* sW4 = (float4*)sm;              // [16][512] float4 = 128KB
    float* h_sh = sm + 16 * 512 * 4;        // [128]
    float* z_sh = h_sh + 128;               // [512]

    int b = blockIdx.x;
    int dir = blockIdx.y;
    const float* Whh = dir ? WhhB : WhhF;
    const float* gin = dir ? g_gin_b : g_gin_f;
    int j = threadIdx.x;

    float wreg[64];
#pragma unroll
    for (int k = 0; k < 64; k++) wreg[k] = Whh[j * HID + k];
#pragma unroll
    for (int k4 = 0; k4 < 16; k4++) {
        float4 w;
        w.x = Whh[j * HID + 64 + k4 * 4 + 0];
        w.y = Whh[j * HID + 64 + k4 * 4 + 1];
        w.z = Whh[j * HID + 64 + k4 * 4 + 2];
        w.w = Whh[j * HID + 64 + k4 * 4 + 3];
        sW4[k4 * 512 + j] = w;
    }
    if (j < HID) h_sh[j] = 0.f;
    float c = 0.f;
    __syncthreads();

    int l0 = dir ? (LL1 - 1) : 0;
    float gcur = gin[((long)l0 * BB + b) * GATES + j];

    for (int s = 0; s < LL1; s++) {
        int l = dir ? (LL1 - 1 - s) : s;
        float gnext = 0.f;
        if (s + 1 < LL1) {
            int ln = dir ? (LL1 - 2 - s) : (s + 1);
            gnext = gin[((long)ln * BB + b) * GATES + j];
        }

        float acc = gcur;
#pragma unroll
        for (int k = 0; k < 64; k += 4) {
            float4 hh = *(const float4*)&h_sh[k];
            acc += hh.x * wreg[k] + hh.y * wreg[k + 1] + hh.z * wreg[k + 2] + hh.w * wreg[k + 3];
        }
#pragma unroll
        for (int k4 = 0; k4 < 16; k4++) {
            float4 hh = *(const float4*)&h_sh[64 + k4 * 4];
            float4 w = sW4[k4 * 512 + j];
            acc += hh.x * w.x + hh.y * w.y + hh.z * w.z + hh.w * w.w;
        }
        z_sh[j] = acc;
        __syncthreads();
        if (j < HID) {
            float zi = z_sh[j], zf = z_sh[j + 128], zg = z_sh[j + 256], zo = z_sh[j + 384];
            float ii = 1.f / (1.f + __expf(-zi));
            float ff = 1.f / (1.f + __expf(-zf));
            float gg = tanhf(zg);
            float oo = 1.f / (1.f + __expf(-zo));
            c = ff * c + ii * gg;
            float h = oo * tanhf(c);
            h_sh[j] = h;
            out[((long)b * LL1 + l) * 256 + dir * HID + j] = h;
        }
        gcur = gnext;
        __syncthreads();
    }
}

// ---------------- launcher ----------------
extern "C" void kernel_launch(void* const* d_in, const int* in_sizes, int n_in,
                              void* d_out, int out_size) {
    const float* x1_word = (const float*)d_in[0];
    const float* x1_a0   = (const float*)d_in[1];
    const float* x1_a1   = (const float*)d_in[2];
    const float* x2_word = (const float*)d_in[3];
    const float* x2_a0   = (const float*)d_in[4];
    const float* x2_a1   = (const float*)d_in[5];
    const float* x2_a2   = (const float*)d_in[6];
    const unsigned char* x2_mask = (const unsigned char*)d_in[8];
    const float* W_attn  = (const float*)d_in[9];
    const float* v_attn  = (const float*)d_in[10];
    const float* Wih_f   = (const float*)d_in[11];
    const float* Whh_f   = (const float*)d_in[12];
    const float* b_f     = (const float*)d_in[13];
    const float* Wih_b   = (const float*)d_in[14];
    const float* Whh_b   = (const float*)d_in[15];
    const float* b_b     = (const float*)d_in[16];
    float* out = (float*)d_out;

    float *x1att, *x2att, *r1, *r2, *scores, *x1cat, *ginf, *ginb;
    cudaGetSymbolAddress((void**)&x1att, g_x1att);
    cudaGetSymbolAddress((void**)&x2att, g_x2att);
    cudaGetSymbolAddress((void**)&r1, g_r1);
    cudaGetSymbolAddress((void**)&r2, g_r2);
    cudaGetSymbolAddress((void**)&scores, g_scores);
    cudaGetSymbolAddress((void**)&x1cat, g_x1cat);
    cudaGetSymbolAddress((void**)&ginf, g_gin_f);
    cudaGetSymbolAddress((void**)&ginb, g_gin_b);

    // concat inputs
    {
        int n1 = BB * LL1 * ATT_IN;
        build_x1att<<<(n1 + 255) / 256, 256>>>(x1_word, x1_a0, x1_a1);
        int n2 = BB * LL2 * ATT_IN;
        build_x2att<<<(n2 + 255) / 256, 256>>>(x2_word, x2_a0, x2_a1);
        int n3 = BB * LL1 * 512;
        build_x1cat_head<<<(n3 + 255) / 256, 256>>>(x1_a0, x1_a1);
    }

    const float* x2_list[3] = {x2_a0, x2_a1, x2_a2};
    for (int i = 0; i < 3; i++) {
        const float* Wi = W_attn + (long)i * ATTD * ATT_IN;
        const float* vi = v_attn + i * ATTD;

        // r1 = relu(x1att @ Wi^T)     [8192 x 250], stride 256
        gemm_tc<<<dim3(2, 64, 1), 256>>>(x1att, ATT_IN, 0, Wi, ATT_IN, 0, 1,
                                         r1, 256, 0, BB * LL1, ATTD, ATT_IN,
                                         nullptr, nullptr, 1, 0);
        // r2 = relu(x2att @ Wi^T) * v
        gemm_tc<<<dim3(2, 64, 1), 256>>>(x2att, ATT_IN, 0, Wi, ATT_IN, 0, 1,
                                         r2, 256, 0, BB * LL2, ATTD, ATT_IN,
                                         nullptr, vi, 1, 0);
        // scores[b] = r1[b] @ r2[b]^T  batched 16 x [512 x 512], K=250
        gemm_tc<<<dim3(4, 4, 16), 256>>>(r1, 256, (long)512 * 256,
                                         r2, 256, (long)512 * 256, 1,
                                         scores, 512, (long)512 * 512,
                                         LL1, LL2, ATTD, nullptr, nullptr, 0, 0);
        // softmax (with x2 mask)
        softmax_rows<<<BB * LL1, 256>>>(x2_mask);
        // piece_i[b] = alpha[b] @ x2_list[i][b] -> x1cat cols [512+256i, +256)
        gemm_tc<<<dim3(2, 4, 16), 256>>>(scores, 512, (long)512 * 512,
                                         x2_list[i], 256, (long)512 * 256, 0,
                                         x1cat + 512 + 256 * i, RNN_IN, (long)512 * RNN_IN,
                                         LL1, AH, LL2, nullptr, nullptr, 0, 0);
    }

    // g_in = x1cat @ Wih^T + b, stored as [l][b][512]
    gemm_tc<<<dim3(4, 64, 1), 256>>>(x1cat, RNN_IN, 0, Wih_f, RNN_IN, 0, 1,
                                     ginf, GATES, 0, BB * LL1, GATES, RNN_IN,
                                     b_f, nullptr, 0, 1);
    gemm_tc<<<dim3(4, 64, 1), 256>>>(x1cat, RNN_IN, 0, Wih_b, RNN_IN, 0, 1,
                                     ginb, GATES, 0, BB * LL1, GATES, RNN_IN,
                                     b_b, nullptr, 0, 1);

    // BiLSTM
    size_t smem = (size_t)(16 * 512 * 4 + 128 + 512) * sizeof(float);
    cudaFuncSetAttribute(lstm_kernel, cudaFuncAttributeMaxDynamicSharedMemorySize, (int)smem);
    lstm_kernel<<<dim3(16, 2), 512, smem>>>(Whh_f, Whh_b, out);
}